// round 1
// baseline (speedup 1.0000x reference)
#include <cuda_runtime.h>
#include <math.h>

// Problem dims (fixed by setup_inputs)
#define BB 2
#define DD 64
#define HH 96
#define WW 96
#define VOL (DD*HH*WW)          // 589824
#define NVOX (BB*VOL)           // 1179648
#define HWSZ (HH*WW)            // 9216
#define BIGF 1e10f

// Scratch (device globals: allocation-free per harness rules)
__device__ float g_fp1[NVOX];
__device__ float g_fn1[NVOX];
__device__ float g_fp2[NVOX];
__device__ float g_fn2[NVOX];
__device__ double g_num[BB];
__device__ double g_den[BB];

__global__ void k_zero() {
    int t = threadIdx.x;
    if (t < BB) { g_num[t] = 0.0; g_den[t] = 0.0; }
}

// Pass 1: along W. target -> squared distance to nearest 0 (fpos) and nearest 1 (fneg).
__global__ void k_pass1(const float* __restrict__ tgt) {
    int idx = blockIdx.x * blockDim.x + threadIdx.x;
    if (idx >= NVOX) return;
    int i = idx % WW;
    const float* t = tgt + (idx - i);
    const int INF = 1 << 30;
    bool one = t[i] > 0.5f;
    int dpos = one ? INF : 0;   // dist to nearest 0
    int dneg = one ? 0 : INF;   // dist to nearest 1
    #pragma unroll 1
    for (int k = 1; k < WW; ++k) {
        if (dpos < INF && dneg < INF) break;
        bool f0 = false, f1 = false;
        if (i - k >= 0) { if (t[i - k] > 0.5f) f1 = true; else f0 = true; }
        if (i + k < WW) { if (t[i + k] > 0.5f) f1 = true; else f0 = true; }
        if (f0 && dpos >= INF) dpos = k;
        if (f1 && dneg >= INF) dneg = k;
    }
    g_fp1[idx] = (dpos >= INF) ? BIGF : (float)(dpos * dpos);
    g_fn1[idx] = (dneg >= INF) ? BIGF : (float)(dneg * dneg);
}

// Pass 2: along H. Exact windowed squared-distance transform:
//   out[i] = min_j f[j] + (i-j)^2, early-exit when k^2 >= current best (f >= 0).
__global__ void k_pass2() {
    int idx = blockIdx.x * blockDim.x + threadIdx.x;
    if (idx >= NVOX) return;
    int w = idx % WW;
    int rest = idx / WW;
    int i = rest % HH;
    int bd = rest / HH;
    const float* fp = g_fp1 + bd * HWSZ + w;
    const float* fn = g_fn1 + bd * HWSZ + w;
    float bp = fp[i * WW];
    float bn = fn[i * WW];
    #pragma unroll 1
    for (int k = 1; k < HH; ++k) {
        float k2 = (float)(k * k);
        if (k2 >= bp && k2 >= bn) break;
        int lo = i - k, hi = i + k;
        if (lo >= 0) {
            bp = fminf(bp, fp[lo * WW] + k2);
            bn = fminf(bn, fn[lo * WW] + k2);
        }
        if (hi < HH) {
            bp = fminf(bp, fp[hi * WW] + k2);
            bn = fminf(bn, fn[hi * WW] + k2);
        }
    }
    g_fp2[idx] = bp;
    g_fn2[idx] = bn;
}

// Pass 3: along D, fused with loss epilogue + reduction.
__global__ void k_pass3(const float* __restrict__ pred, const float* __restrict__ tgt) {
    int idx = blockIdx.x * blockDim.x + threadIdx.x;
    int b = idx / VOL;
    int inner = idx % VOL;
    int i = inner / HWSZ;
    int hw = inner % HWSZ;
    const float* fp = g_fp2 + b * VOL + hw;
    const float* fn = g_fn2 + b * VOL + hw;
    float bp = fp[i * HWSZ];
    float bn = fn[i * HWSZ];
    #pragma unroll 1
    for (int k = 1; k < DD; ++k) {
        float k2 = (float)(k * k);
        if (k2 >= bp && k2 >= bn) break;
        int lo = i - k, hi = i + k;
        if (lo >= 0) {
            bp = fminf(bp, fp[lo * HWSZ] + k2);
            bn = fminf(bn, fn[lo * HWSZ] + k2);
        }
        if (hi < DD) {
            bp = fminf(bp, fp[hi * HWSZ] + k2);
            bn = fminf(bn, fn[hi * HWSZ] + k2);
        }
    }
    float dp = sqrtf(bp);
    float dn = sqrtf(bn);
    float a = fabsf(dn - dp);
    float wgt = (a <= 3.0f) ? 1.0f : ((a >= 5.0f) ? 0.0f : (1.0f - (a - 3.0f) * 0.5f));
    float p = pred[idx];
    float t = tgt[idx];
    float lp  = fmaxf(logf(p), -100.0f);
    float l1p = fmaxf(logf(1.0f - p), -100.0f);
    float bce = -(t * lp + (1.0f - t) * l1p);

    // Block reduction (each 256-thread block lies entirely within one batch:
    // 256 | VOL), then one double atomicAdd per block.
    __shared__ double sn[256];
    __shared__ double sd[256];
    int tid = threadIdx.x;
    sn[tid] = (double)(bce * wgt);
    sd[tid] = (double)wgt;
    __syncthreads();
    #pragma unroll
    for (int s = 128; s > 0; s >>= 1) {
        if (tid < s) { sn[tid] += sn[tid + s]; sd[tid] += sd[tid + s]; }
        __syncthreads();
    }
    if (tid == 0) {
        atomicAdd(&g_num[b], sn[0]);
        atomicAdd(&g_den[b], sd[0]);
    }
}

__global__ void k_final(float* __restrict__ out) {
    double acc = 0.0;
    #pragma unroll
    for (int b = 0; b < BB; ++b) acc += g_num[b] / (g_den[b] + 1e-5);
    out[0] = (float)(acc / (double)BB);
}

extern "C" void kernel_launch(void* const* d_in, const int* in_sizes, int n_in,
                              void* d_out, int out_size) {
    const float* pred = (const float*)d_in[0];
    const float* tgt  = (const float*)d_in[1];
    (void)in_sizes; (void)n_in; (void)out_size;

    const int threads = 256;
    const int blocks = NVOX / threads;  // 4608, exact

    k_zero<<<1, 32>>>();
    k_pass1<<<blocks, threads>>>(tgt);
    k_pass2<<<blocks, threads>>>();
    k_pass3<<<blocks, threads>>>(pred, tgt);
    k_final<<<1, 1>>>((float*)d_out);
}

// round 2
// speedup vs baseline: 2.2007x; 2.2007x over previous
#include <cuda_runtime.h>
#include <math.h>

// Problem dims (fixed by setup_inputs)
#define BB 2
#define DD 64
#define HH 96
#define WW 96
#define VOL (DD*HH*WW)          // 589824
#define NVOX (BB*VOL)           // 1179648
#define HWSZ (HH*WW)            // 9216
#define BIGF 1e10f
#define WT 32                   // w-tile width (one warp lane per w)

// Scratch (device globals: allocation-free per harness rules)
__device__ float g_fp1[NVOX];
__device__ float g_fn1[NVOX];
__device__ float g_fp2[NVOX];
__device__ float g_fn2[NVOX];
__device__ double g_num[BB];
__device__ double g_den[BB];

__global__ void k_zero() {
    int t = threadIdx.x;
    if (t < BB) { g_num[t] = 0.0; g_den[t] = 0.0; }
}

// Pass 1: along W (contiguous). target -> squared distance to nearest 0 (fpos)
// and nearest 1 (fneg).
__global__ void k_pass1(const float* __restrict__ tgt) {
    int idx = blockIdx.x * blockDim.x + threadIdx.x;
    if (idx >= NVOX) return;
    int i = idx % WW;
    const float* t = tgt + (idx - i);
    const int INF = 1 << 30;
    bool one = t[i] > 0.5f;
    int dpos = one ? INF : 0;   // dist to nearest 0
    int dneg = one ? 0 : INF;   // dist to nearest 1
    #pragma unroll 1
    for (int k = 1; k < WW; ++k) {
        if (dpos < INF && dneg < INF) break;
        bool f0 = false, f1 = false;
        if (i - k >= 0) { if (t[i - k] > 0.5f) f1 = true; else f0 = true; }
        if (i + k < WW) { if (t[i + k] > 0.5f) f1 = true; else f0 = true; }
        if (f0 && dpos >= INF) dpos = k;
        if (f1 && dneg >= INF) dneg = k;
    }
    g_fp1[idx] = (dpos >= INF) ? BIGF : (float)(dpos * dpos);
    g_fn1[idx] = (dneg >= INF) ? BIGF : (float)(dneg * dneg);
}

// Pass 2: along H, staged in shared memory.
// Block = one (b,d) plane slice of 32 consecutive w. Tile [HH][32].
__global__ __launch_bounds__(256) void k_pass2() {
    __shared__ float sfp[HH][WT];
    __shared__ float sfn[HH][WT];

    int wt = blockIdx.x % (WW / WT);
    int bd = blockIdx.x / (WW / WT);
    int w0 = wt * WT;
    int base = bd * HWSZ + w0;
    int tid = threadIdx.x;

    // Coalesced tile load: consecutive threads -> consecutive w.
    #pragma unroll
    for (int r = tid; r < HH * WT; r += 256) {
        int h = r / WT, w = r % WT;
        sfp[h][w] = g_fp1[base + h * WW + w];
        sfn[h][w] = g_fn1[base + h * WW + w];
    }
    __syncthreads();

    int w = tid & 31;
    int h0 = tid >> 5;  // 0..7
    #pragma unroll 1
    for (int i = h0; i < HH; i += 8) {
        float bp = sfp[i][w];
        float bn = sfn[i][w];
        #pragma unroll 1
        for (int k = 1; k < HH; ++k) {
            float k2 = (float)(k * k);
            if (k2 >= bp && k2 >= bn) break;
            int lo = i - k, hi = i + k;
            if (lo >= 0) {
                bp = fminf(bp, sfp[lo][w] + k2);
                bn = fminf(bn, sfn[lo][w] + k2);
            }
            if (hi < HH) {
                bp = fminf(bp, sfp[hi][w] + k2);
                bn = fminf(bn, sfn[hi][w] + k2);
            }
        }
        g_fp2[base + i * WW + w] = bp;   // coalesced per warp
        g_fn2[base + i * WW + w] = bn;
    }
}

// Pass 3: along D, staged in shared memory, fused with loss epilogue + reduction.
// Block = one (b,h) column set of 32 consecutive w. Tile [DD][32].
__global__ __launch_bounds__(256) void k_pass3(const float* __restrict__ pred,
                                               const float* __restrict__ tgt) {
    __shared__ float sfp[DD][WT];
    __shared__ float sfn[DD][WT];
    __shared__ float rn[8], rd[8];

    int wt = blockIdx.x % (WW / WT);
    int bh = blockIdx.x / (WW / WT);
    int b = bh / HH;
    int h = bh % HH;
    int w0 = wt * WT;
    int base = b * VOL + h * WW + w0;
    int tid = threadIdx.x;

    #pragma unroll
    for (int r = tid; r < DD * WT; r += 256) {
        int d = r / WT, w = r % WT;
        sfp[d][w] = g_fp2[base + d * HWSZ + w];
        sfn[d][w] = g_fn2[base + d * HWSZ + w];
    }
    __syncthreads();

    int w = tid & 31;
    int d0 = tid >> 5;  // 0..7
    float accn = 0.0f, accd = 0.0f;

    #pragma unroll 1
    for (int i = d0; i < DD; i += 8) {
        float bp = sfp[i][w];
        float bn = sfn[i][w];
        #pragma unroll 1
        for (int k = 1; k < DD; ++k) {
            float k2 = (float)(k * k);
            if (k2 >= bp && k2 >= bn) break;
            int lo = i - k, hi = i + k;
            if (lo >= 0) {
                bp = fminf(bp, sfp[lo][w] + k2);
                bn = fminf(bn, sfn[lo][w] + k2);
            }
            if (hi < DD) {
                bp = fminf(bp, sfp[hi][w] + k2);
                bn = fminf(bn, sfn[hi][w] + k2);
            }
        }
        float dp = sqrtf(bp);
        float dn = sqrtf(bn);
        float a = fabsf(dn - dp);
        float wgt = (a <= 3.0f) ? 1.0f : ((a >= 5.0f) ? 0.0f : (1.0f - (a - 3.0f) * 0.5f));

        int idx = base + i * HWSZ + w;      // coalesced per warp
        float p = pred[idx];
        float t = tgt[idx];
        float lp  = fmaxf(__logf(p), -100.0f);
        float l1p = fmaxf(__logf(1.0f - p), -100.0f);
        float bce = -(t * lp + (1.0f - t) * l1p);
        accn += bce * wgt;
        accd += wgt;
    }

    // Warp shuffle reduction, then cross-warp via smem, one double atomic per block.
    #pragma unroll
    for (int off = 16; off > 0; off >>= 1) {
        accn += __shfl_down_sync(0xFFFFFFFFu, accn, off);
        accd += __shfl_down_sync(0xFFFFFFFFu, accd, off);
    }
    if (w == 0) { rn[d0] = accn; rd[d0] = accd; }
    __syncthreads();
    if (tid == 0) {
        float sn = 0.0f, sd = 0.0f;
        #pragma unroll
        for (int j = 0; j < 8; ++j) { sn += rn[j]; sd += rd[j]; }
        atomicAdd(&g_num[b], (double)sn);
        atomicAdd(&g_den[b], (double)sd);
    }
}

__global__ void k_final(float* __restrict__ out) {
    double acc = 0.0;
    #pragma unroll
    for (int b = 0; b < BB; ++b) acc += g_num[b] / (g_den[b] + 1e-5);
    out[0] = (float)(acc / (double)BB);
}

extern "C" void kernel_launch(void* const* d_in, const int* in_sizes, int n_in,
                              void* d_out, int out_size) {
    const float* pred = (const float*)d_in[0];
    const float* tgt  = (const float*)d_in[1];
    (void)in_sizes; (void)n_in; (void)out_size;

    k_zero<<<1, 32>>>();
    k_pass1<<<NVOX / 256, 256>>>(tgt);
    k_pass2<<<(BB * DD) * (WW / WT), 256>>>();                 // 384 blocks
    k_pass3<<<(BB * HH) * (WW / WT), 256>>>(pred, tgt);        // 576 blocks
    k_final<<<1, 1>>>((float*)d_out);
}